// round 1
// baseline (speedup 1.0000x reference)
#include <cuda_runtime.h>

// Problem constants (fixed shapes)
#define BS    16
#define DIM   4096
#define NH    32
#define DH    128
#define SEQ   4096
#define NCOL  4096   // NH*DH
#define KS    4      // K-split for the 16xN GEMMs

#define WEIGHT_ELEMS (BS * NH * SEQ)   // 2097152 (pre-softmax scores output)
#define BN (BS * NCOL)                 // 65536

// Scratch (device globals; no allocation allowed)
__device__ float g_qkv[3 * BN];        // q,k,v : [mat][b][h*128+d]
__device__ float g_part[3 * KS * BN];  // qkv GEMM k-split partials
__device__ float g_ctx[BN];            // attention context [b][h*128+d]
__device__ float g_cpart[KS * BN];     // out-proj k-split partials

// ---------------------------------------------------------------------------
// 16xK @ KxN GEMM body: 128 threads, each thread owns one output column j for
// all 16 batch rows. X rows staged through smem; W read fully coalesced.
// Writes a k-split partial (deterministic; no atomics).
// ---------------------------------------------------------------------------
__device__ __forceinline__ void gemm16_body(const float* __restrict__ X,
                                            const float* __restrict__ W,
                                            float* __restrict__ part)
{
    __shared__ __align__(16) float xs[64][16];
    const int j  = blockIdx.x * 128 + threadIdx.x;
    const int d0 = blockIdx.y * (DIM / KS);

    float acc[16];
#pragma unroll
    for (int b = 0; b < 16; b++) acc[b] = 0.f;

    for (int dt = 0; dt < DIM / KS; dt += 64) {
        const int base = d0 + dt;
#pragma unroll
        for (int i = threadIdx.x; i < 1024; i += 128) {
            int b = i >> 6, dd = i & 63;
            xs[dd][b] = X[b * DIM + base + dd];
        }
        __syncthreads();
#pragma unroll 8
        for (int dd = 0; dd < 64; dd++) {
            float w = W[(size_t)(base + dd) * NCOL + j];
            const float4* xv = (const float4*)xs[dd];
            float4 v0 = xv[0], v1 = xv[1], v2 = xv[2], v3 = xv[3];
            acc[0]  += v0.x * w; acc[1]  += v0.y * w; acc[2]  += v0.z * w; acc[3]  += v0.w * w;
            acc[4]  += v1.x * w; acc[5]  += v1.y * w; acc[6]  += v1.z * w; acc[7]  += v1.w * w;
            acc[8]  += v2.x * w; acc[9]  += v2.y * w; acc[10] += v2.z * w; acc[11] += v2.w * w;
            acc[12] += v3.x * w; acc[13] += v3.y * w; acc[14] += v3.z * w; acc[15] += v3.w * w;
        }
        __syncthreads();
    }
#pragma unroll
    for (int b = 0; b < 16; b++) part[b * NCOL + j] = acc[b];
}

__global__ __launch_bounds__(128)
void gemm_qkv(const float* __restrict__ x, const float* __restrict__ wq,
              const float* __restrict__ wk, const float* __restrict__ wv)
{
    const float* W = (blockIdx.z == 0) ? wq : (blockIdx.z == 1 ? wk : wv);
    float* part = g_part + ((size_t)blockIdx.z * KS + blockIdx.y) * BN;
    gemm16_body(x, W, part);
}

__global__ __launch_bounds__(128)
void gemm_out(const float* __restrict__ wo)
{
    float* part = g_cpart + (size_t)blockIdx.y * BN;
    gemm16_body(g_ctx, wo, part);
}

__global__ __launch_bounds__(256)
void reduce_qkv()
{
    int i = blockIdx.x * 256 + threadIdx.x;
    if (i < 3 * BN) {
        int mat = i >> 16;           // /65536
        int r   = i & (BN - 1);
        const float* p = g_part + (size_t)mat * KS * BN;
        g_qkv[i] = p[r] + p[BN + r] + p[2 * BN + r] + p[3 * BN + r];
    }
}

__global__ __launch_bounds__(256)
void reduce_out(float* __restrict__ out)
{
    int i = blockIdx.x * 256 + threadIdx.x;
    if (i < BN)
        out[i] = g_cpart[i] + g_cpart[BN + i] + g_cpart[2 * BN + i] + g_cpart[3 * BN + i];
}

// ---------------------------------------------------------------------------
// Fused attention per (b,h): scores (warp-per-k, shfl reduce) -> write weight
// output -> block softmax -> ctx (thread-per-d over cache_v).
// k == 4095 uses the freshly projected xk / xv (cache update semantics).
// ---------------------------------------------------------------------------
__global__ __launch_bounds__(256)
void attn_kernel(const float* __restrict__ ck, const float* __restrict__ cv,
                 const float* __restrict__ mask, float* __restrict__ out)
{
    const int b = blockIdx.x, h = blockIdx.y;
    const int tid = threadIdx.x, lane = tid & 31, wp = tid >> 5;

    __shared__ float sc[SEQ];          // scores -> exp weights
    __shared__ __align__(16) float qs[DH];
    __shared__ float redm[8], reds[8];
    __shared__ float cp[2][DH];

    if (tid < DH) qs[tid] = g_qkv[(size_t)b * NCOL + h * DH + tid];
    __syncthreads();

    const float4 qf = ((const float4*)qs)[lane];
    const float* kbase = ck + ((size_t)b << 24) + (size_t)h * DH;   // b*SEQ*NCOL
    const float* knew  = g_qkv + BN + (size_t)b * NCOL + h * DH;    // xk row
    const float scale = 0.08838834764831845f;                        // 1/sqrt(128)
    float* wout = out + ((size_t)(b * NH + h)) * SEQ;

    // pass 1: scores
#pragma unroll 4
    for (int k = wp; k < SEQ; k += 8) {
        const float* row = (k == SEQ - 1) ? knew : (kbase + (size_t)k * NCOL);
        float4 kf = ((const float4*)row)[lane];
        float p = kf.x * qf.x + kf.y * qf.y + kf.z * qf.z + kf.w * qf.w;
        p += __shfl_xor_sync(0xffffffffu, p, 16);
        p += __shfl_xor_sync(0xffffffffu, p, 8);
        p += __shfl_xor_sync(0xffffffffu, p, 4);
        p += __shfl_xor_sync(0xffffffffu, p, 2);
        p += __shfl_xor_sync(0xffffffffu, p, 1);
        if (lane == 0) {
            float s = p * scale + mask[k];
            sc[k]   = s;
            wout[k] = s;   // pre-softmax "weight" output
        }
    }
    __syncthreads();

    // softmax (max, exp, sum)
    float m = -1e30f;
    for (int i = tid; i < SEQ; i += 256) m = fmaxf(m, sc[i]);
#pragma unroll
    for (int o = 16; o; o >>= 1) m = fmaxf(m, __shfl_xor_sync(0xffffffffu, m, o));
    if (lane == 0) redm[wp] = m;
    __syncthreads();
    float M = redm[0];
#pragma unroll
    for (int i = 1; i < 8; i++) M = fmaxf(M, redm[i]);

    float sum = 0.f;
    for (int i = tid; i < SEQ; i += 256) {
        float e = __expf(sc[i] - M);
        sc[i] = e;
        sum += e;
    }
#pragma unroll
    for (int o = 16; o; o >>= 1) sum += __shfl_xor_sync(0xffffffffu, sum, o);
    if (lane == 0) reds[wp] = sum;
    __syncthreads();
    float S = reds[0] + reds[1] + reds[2] + reds[3] +
              reds[4] + reds[5] + reds[6] + reds[7];
    const float rinv = 1.f / S;

    // pass 2: ctx[d] = sum_k attn[k] * V[b,k,h,d]
    const int d  = tid & 127;
    const int kh = tid >> 7;
    const float* vbase = cv + ((size_t)b << 24) + (size_t)h * DH + d;
    float acc = 0.f;
    const int k0 = kh * 2048;
    const int k1 = k0 + 2048 - kh;     // kh==1 stops at 4094 (4095 handled below)
#pragma unroll 8
    for (int k = k0; k < k1; k++)
        acc += sc[k] * vbase[(size_t)k * NCOL];
    if (kh)
        acc += sc[SEQ - 1] * g_qkv[2 * BN + (size_t)b * NCOL + h * DH + d];

    cp[kh][d] = acc;
    __syncthreads();
    if (tid < DH)
        g_ctx[(size_t)b * NCOL + h * DH + tid] = (cp[0][tid] + cp[1][tid]) * rinv;
}

// ---------------------------------------------------------------------------
extern "C" void kernel_launch(void* const* d_in, const int* in_sizes, int n_in,
                              void* d_out, int out_size)
{
    const float* x    = (const float*)d_in[0];
    const float* mask = (const float*)d_in[1];
    const float* wq   = (const float*)d_in[2];
    const float* wk   = (const float*)d_in[3];
    const float* wv   = (const float*)d_in[4];
    const float* wo   = (const float*)d_in[5];
    const float* ck   = (const float*)d_in[6];
    const float* cv   = (const float*)d_in[7];
    float* out = (float*)d_out;

    gemm_qkv<<<dim3(32, KS, 3), 128>>>(x, wq, wk, wv);
    reduce_qkv<<<(3 * BN) / 256, 256>>>();
    attn_kernel<<<dim3(BS, NH), 256>>>(ck, cv, mask, out);
    gemm_out<<<dim3(32, KS, 1), 128>>>(wo);
    reduce_out<<<BN / 256, 256>>>(out + WEIGHT_ELEMS);
}

// round 2
// speedup vs baseline: 2.3926x; 2.3926x over previous
#include <cuda_runtime.h>

// Problem constants (fixed shapes)
#define BS    16
#define DIM   4096
#define NH    32
#define DH    128
#define SEQ   4096
#define NCOL  4096   // NH*DH
#define KS    64     // K-split for the 16xN GEMMs

#define WEIGHT_ELEMS (BS * NH * SEQ)   // 2097152 (pre-softmax scores output)
#define BN (BS * NCOL)                 // 65536

// Scratch (device globals; no allocation allowed)
__device__ float g_qkv[3 * BN];             // q,k,v : [mat][b][h*128+d]
__device__ float g_part[3 * KS * BN];       // qkv GEMM k-split partials (48MB)
__device__ float g_ctx[BN];                 // attention context [b][h*128+d]
__device__ float g_cpart[KS * BN];          // out-proj k-split partials (16MB)

// ---------------------------------------------------------------------------
// 16xK @ KxN GEMM body: 128 threads, each thread owns 4 consecutive output
// columns (float4 W loads) for all 16 batch rows. Block covers 512 columns
// and DIM/KS = 64 K-rows. X staged in smem (broadcast reads).
// ---------------------------------------------------------------------------
__device__ __forceinline__ void gemm16_body(const float* __restrict__ X,
                                            const float* __restrict__ W,
                                            float* __restrict__ part)
{
    __shared__ __align__(16) float xs[32][16];
    const int j4 = blockIdx.x * 512 + threadIdx.x * 4;   // first of 4 columns
    const int d0 = blockIdx.y * (DIM / KS);              // 64 rows per split

    float4 acc[16];
#pragma unroll
    for (int b = 0; b < 16; b++) acc[b] = make_float4(0.f, 0.f, 0.f, 0.f);

    const float4* W4 = (const float4*)W;

    for (int dt = 0; dt < DIM / KS; dt += 32) {
        const int base = d0 + dt;
        // stage 32 rows x 16 batch of X
#pragma unroll
        for (int i = threadIdx.x; i < 512; i += 128) {
            int b = i >> 5, dd = i & 31;
            xs[dd][b] = X[b * DIM + base + dd];
        }
        __syncthreads();
#pragma unroll 4
        for (int dd = 0; dd < 32; dd++) {
            float4 w = W4[(size_t)(base + dd) * (NCOL / 4) + (j4 >> 2)];
            const float4* xv = (const float4*)xs[dd];
#pragma unroll
            for (int b4 = 0; b4 < 4; b4++) {
                float4 xb = xv[b4];
                acc[b4 * 4 + 0].x += xb.x * w.x; acc[b4 * 4 + 0].y += xb.x * w.y;
                acc[b4 * 4 + 0].z += xb.x * w.z; acc[b4 * 4 + 0].w += xb.x * w.w;
                acc[b4 * 4 + 1].x += xb.y * w.x; acc[b4 * 4 + 1].y += xb.y * w.y;
                acc[b4 * 4 + 1].z += xb.y * w.z; acc[b4 * 4 + 1].w += xb.y * w.w;
                acc[b4 * 4 + 2].x += xb.z * w.x; acc[b4 * 4 + 2].y += xb.z * w.y;
                acc[b4 * 4 + 2].z += xb.z * w.z; acc[b4 * 4 + 2].w += xb.z * w.w;
                acc[b4 * 4 + 3].x += xb.w * w.x; acc[b4 * 4 + 3].y += xb.w * w.y;
                acc[b4 * 4 + 3].z += xb.w * w.z; acc[b4 * 4 + 3].w += xb.w * w.w;
            }
        }
        __syncthreads();
    }
    float4* P4 = (float4*)part;
#pragma unroll
    for (int b = 0; b < 16; b++) P4[b * (NCOL / 4) + (j4 >> 2)] = acc[b];
}

__global__ __launch_bounds__(128)
void gemm_qkv(const float* __restrict__ x, const float* __restrict__ wq,
              const float* __restrict__ wk, const float* __restrict__ wv)
{
    const float* W = (blockIdx.z == 0) ? wq : (blockIdx.z == 1 ? wk : wv);
    float* part = g_part + ((size_t)blockIdx.z * KS + blockIdx.y) * BN;
    gemm16_body(x, W, part);
}

__global__ __launch_bounds__(128)
void gemm_out(const float* __restrict__ wo)
{
    float* part = g_cpart + (size_t)blockIdx.y * BN;
    gemm16_body(g_ctx, wo, part);
}

__global__ __launch_bounds__(256)
void reduce_qkv()
{
    int i = blockIdx.x * 256 + threadIdx.x;
    if (i < 3 * BN) {
        int mat = i >> 16;           // /65536
        int r   = i & (BN - 1);
        const float* p = g_part + (size_t)mat * KS * BN + r;
        float s = 0.f;
#pragma unroll 8
        for (int k = 0; k < KS; k++) s += p[(size_t)k * BN];
        g_qkv[i] = s;
    }
}

__global__ __launch_bounds__(256)
void reduce_out(float* __restrict__ out)
{
    int i = blockIdx.x * 256 + threadIdx.x;
    if (i < BN) {
        const float* p = g_cpart + i;
        float s = 0.f;
#pragma unroll 8
        for (int k = 0; k < KS; k++) s += p[(size_t)k * BN];
        out[i] = s;
    }
}

// ---------------------------------------------------------------------------
// Fused attention per (b,h), 512 threads.
// pass1: warp-per-k (float4 K loads, shfl reduce) -> scores into smem
// coalesced weight write + softmax -> pass2: 16 k-stripes x 32-lane float4
// V loads. k == 4095 redirected to fresh xk/xv (cache update semantics).
// ---------------------------------------------------------------------------
__global__ __launch_bounds__(512)
void attn_kernel(const float* __restrict__ ck, const float* __restrict__ cv,
                 const float* __restrict__ mask, float* __restrict__ out)
{
    const int b = blockIdx.x, h = blockIdx.y;
    const int tid = threadIdx.x, lane = tid & 31, wp = tid >> 5;

    __shared__ float sc[SEQ];          // scores -> exp weights
    __shared__ __align__(16) float qs[DH];
    __shared__ float redm[16], reds[16];
    __shared__ __align__(16) float cp[16][DH];

    if (tid < DH) qs[tid] = g_qkv[(size_t)b * NCOL + h * DH + tid];
    __syncthreads();

    const float4 qf = ((const float4*)qs)[lane];
    const float* kbase = ck + ((size_t)b << 24) + (size_t)h * DH;   // b*SEQ*NCOL
    const float* knew  = g_qkv + BN + (size_t)b * NCOL + h * DH;    // xk row
    const float scale = 0.08838834764831845f;                        // 1/sqrt(128)
    float* wout = out + ((size_t)(b * NH + h)) * SEQ;

    // pass 1: scores (16 warps, 256 rows each)
#pragma unroll 4
    for (int k = wp; k < SEQ; k += 16) {
        const float* row = (k == SEQ - 1) ? knew : (kbase + (size_t)k * NCOL);
        float4 kf = ((const float4*)row)[lane];
        float p = kf.x * qf.x + kf.y * qf.y + kf.z * qf.z + kf.w * qf.w;
        p += __shfl_xor_sync(0xffffffffu, p, 16);
        p += __shfl_xor_sync(0xffffffffu, p, 8);
        p += __shfl_xor_sync(0xffffffffu, p, 4);
        p += __shfl_xor_sync(0xffffffffu, p, 2);
        p += __shfl_xor_sync(0xffffffffu, p, 1);
        if (lane == 0) sc[k] = p * scale + mask[k];
    }
    __syncthreads();

    // coalesced weight output write + max reduce
    float m = -1e30f;
    for (int i = tid; i < SEQ; i += 512) {
        float s = sc[i];
        wout[i] = s;
        m = fmaxf(m, s);
    }
#pragma unroll
    for (int o = 16; o; o >>= 1) m = fmaxf(m, __shfl_xor_sync(0xffffffffu, m, o));
    if (lane == 0) redm[wp] = m;
    __syncthreads();
    float M = redm[0];
#pragma unroll
    for (int i = 1; i < 16; i++) M = fmaxf(M, redm[i]);

    float sum = 0.f;
    for (int i = tid; i < SEQ; i += 512) {
        float e = __expf(sc[i] - M);
        sc[i] = e;
        sum += e;
    }
#pragma unroll
    for (int o = 16; o; o >>= 1) sum += __shfl_xor_sync(0xffffffffu, sum, o);
    if (lane == 0) reds[wp] = sum;
    __syncthreads();
    float S = 0.f;
#pragma unroll
    for (int i = 0; i < 16; i++) S += reds[i];
    const float rinv = 1.f / S;

    // pass 2: ctx[d] = sum_k attn[k] * V[b,k,h,d]; 16 k-stripes, float4 loads
    const float4* vrow4 = (const float4*)(cv + ((size_t)b << 24) + (size_t)h * DH);
    float4 a4 = make_float4(0.f, 0.f, 0.f, 0.f);
    const int k0 = wp * 256;
    const int k1 = k0 + 256 - (wp == 15 ? 1 : 0);   // stripe 15 stops at 4094
#pragma unroll 8
    for (int k = k0; k < k1; k++) {
        float w = sc[k];
        float4 v = vrow4[(size_t)k * (NCOL / 4) + lane];
        a4.x += w * v.x; a4.y += w * v.y; a4.z += w * v.z; a4.w += w * v.w;
    }
    if (wp == 15) {
        float w = sc[SEQ - 1];
        float4 v = ((const float4*)(g_qkv + 2 * BN + (size_t)b * NCOL + h * DH))[lane];
        a4.x += w * v.x; a4.y += w * v.y; a4.z += w * v.z; a4.w += w * v.w;
    }
    ((float4*)cp[wp])[lane] = a4;
    __syncthreads();

    if (tid < DH) {
        float s = 0.f;
#pragma unroll
        for (int i = 0; i < 16; i++) s += cp[i][tid];
        g_ctx[(size_t)b * NCOL + h * DH + tid] = s * rinv;
    }
}

// ---------------------------------------------------------------------------
extern "C" void kernel_launch(void* const* d_in, const int* in_sizes, int n_in,
                              void* d_out, int out_size)
{
    const float* x    = (const float*)d_in[0];
    const float* mask = (const float*)d_in[1];
    const float* wq   = (const float*)d_in[2];
    const float* wk   = (const float*)d_in[3];
    const float* wv   = (const float*)d_in[4];
    const float* wo   = (const float*)d_in[5];
    const float* ck   = (const float*)d_in[6];
    const float* cv   = (const float*)d_in[7];
    float* out = (float*)d_out;

    gemm_qkv<<<dim3(8, KS, 3), 128>>>(x, wq, wk, wv);
    reduce_qkv<<<(3 * BN) / 256, 256>>>();
    attn_kernel<<<dim3(BS, NH), 512>>>(ck, cv, mask, out);
    gemm_out<<<dim3(8, KS, 1), 128>>>(wo);
    reduce_out<<<BN / 256, 256>>>(out + WEIGHT_ELEMS);
}